// round 17
// baseline (speedup 1.0000x reference)
#include <cuda_runtime.h>
#include <cuda_fp16.h>
#include <cstdint>

// KPConv warp-MMA GEMM: pair-split single-pass fp16, software-pipelined,
// 5 CTAs/SM.  Per iteration: ldsm(t0) -> build A(next) -> prefetch x ->
// mma(t0) -> ldsm(t1) -> mma(t1) -> STG -> bar.  Double-buffered A staging.
//   A[p, j] = exp(-0.5*d2(p,k)/sigma^2) * x[p,i]  (j=3k+i, 48 cols, 3 k-tiles)
//   out = A @ W   (both rounded once to fp16, fp32 accum; rel_err ~2.9e-4)

#define KP_    16
#define JDIM   48
#define COUT_  64
#define NTHR   128
#define ROWB   144
#define AWARP  (16 * ROWB)   // 2304 B per warp tile

__device__ __forceinline__ uint32_t smem_u32(const void* p) {
    uint32_t a;
    asm("{ .reg .u64 t; cvta.to.shared.u64 t, %1; cvt.u32.u64 %0, t; }" : "=r"(a) : "l"(p));
    return a;
}
__device__ __forceinline__ uint32_t pack_h_rn(float lo, float hi) {
    uint32_t r;
    asm("cvt.rn.f16x2.f32 %0, %1, %2;" : "=r"(r) : "f"(hi), "f"(lo));
    return r;
}
__device__ __forceinline__ void ldsm_x4(uint32_t* r, uint32_t addr) {
    asm volatile("ldmatrix.sync.aligned.m8n8.x4.shared.b16 {%0,%1,%2,%3}, [%4];"
                 : "=r"(r[0]), "=r"(r[1]), "=r"(r[2]), "=r"(r[3]) : "r"(addr));
}
__device__ __forceinline__ void mma_f16(float* c, const uint32_t* a, const uint32_t* b) {
    asm volatile(
        "mma.sync.aligned.m16n8k16.row.col.f32.f16.f16.f32 "
        "{%0,%1,%2,%3}, {%4,%5,%6,%7}, {%8,%9}, {%0,%1,%2,%3};"
        : "+f"(c[0]), "+f"(c[1]), "+f"(c[2]), "+f"(c[3])
        : "r"(a[0]), "r"(a[1]), "r"(a[2]), "r"(a[3]), "r"(b[0]), "r"(b[1]));
}
__device__ __forceinline__ float ex2f(float a) {
    float r;
    asm("ex2.approx.f32 %0, %1;" : "=f"(r) : "f"(a));
    return r;
}
__device__ __forceinline__ void bar_pair(int id) {
    asm volatile("bar.sync %0, 64;" :: "r"(id) : "memory");
}

__global__ __launch_bounds__(NTHR, 5)
void kpconv_pipe2_kernel(const float* __restrict__ x,
                         const float* __restrict__ kpts,
                         const float* __restrict__ wts,
                         const float* __restrict__ sigma,
                         float* __restrict__ out,
                         int npts)
{
    // [buf][warp][16 rows x 144B] = 18432 B; W (12288B) staged aliased.
    __shared__ __align__(16) char sA[2][4][AWARP];
    __shared__ float4 sKP4[KP_];

    const int tid  = threadIdx.x;
    const int wid  = tid >> 5;
    const int lane = tid & 31;
    const int gid  = lane >> 2;     // 0..7
    const int tig  = lane & 3;      // 0..3
    const int pr   = wid >> 1;      // pair id 0/1
    const int j    = wid & 1;       // n-half within pair
    const int colbase = 32 * j;

    if (tid < KP_)
        sKP4[tid] = make_float4(kpts[3 * tid], kpts[3 * tid + 1], kpts[3 * tid + 2], 0.f);

    // ---- one-time: stage W (aliased into sA), build this lane's fp16 B frags ----
    float* sWf = reinterpret_cast<float*>(&sA[0][0][0]);
    for (int i = tid; i < JDIM * COUT_; i += NTHR) sWf[i] = wts[i];
    __syncthreads();

    uint32_t B[4][3][2];
#pragma unroll
    for (int nt = 0; nt < 4; nt++) {
#pragma unroll
        for (int kt = 0; kt < 3; kt++) {
            int n  = colbase + nt * 8 + gid;
            int j0 = kt * 16 + 2 * tig;
#pragma unroll
            for (int h = 0; h < 2; h++) {
                float w0 = sWf[(j0 + 8 * h    ) * COUT_ + n];
                float w1 = sWf[(j0 + 8 * h + 1) * COUT_ + n];
                B[nt][kt][h] = pack_h_rn(w0, w1);
            }
        }
    }
    __syncthreads();   // W staging dead; sA belongs to pairs now

    const float sg  = sigma[0];
    const float cc2 = -0.72134752f / (sg * sg);   // -0.5*log2(e)/sigma^2

    const uint32_t lmoff = (uint32_t)(lane & 15) * ROWB + (uint32_t)(lane >> 4) * 16;
    const uint32_t sbase = smem_u32(&sA[0][0][0]);

    const int ngroups = (npts + 31) >> 5;
    const int g0      = blockIdx.x * 2 + pr;
    const int gstep   = gridDim.x * 2;
    const int barid   = pr + 1;
    const int r       = lane >> 1;        // my staging row
    const int kh      = lane & 1;         // my k-half

    auto build_A = [&](int b, float x0, float x1, float x2) {
        float a[24];
#pragma unroll
        for (int kk = 0; kk < 8; kk++) {
            const float4 kp = sKP4[8 * kh + kk];
            float dx = x0 - kp.x, dy = x1 - kp.y, dz = x2 - kp.z;
            float d2 = fmaf(dx, dx, fmaf(dy, dy, dz * dz));
            float g  = ex2f(cc2 * d2);
            a[3 * kk] = g * x0; a[3 * kk + 1] = g * x1; a[3 * kk + 2] = g * x2;
        }
        uint32_t hv[12];
#pragma unroll
        for (int m = 0; m < 12; m++)
            hv[m] = pack_h_rn(a[2 * m], a[2 * m + 1]);
        char* rh = &sA[b][wid][0] + r * ROWB + kh * 48;
#pragma unroll
        for (int q = 0; q < 3; q++)
            *reinterpret_cast<uint4*>(rh + q * 16) =
                make_uint4(hv[4 * q], hv[4 * q + 1], hv[4 * q + 2], hv[4 * q + 3]);
    };
    auto load_x = [&](int g, float& x0, float& x1, float& x2) {
        x0 = 0.f; x1 = 0.f; x2 = 0.f;
        if (g < ngroups) {
            const int p = (g << 5) + j * 16 + r;
            if (p < npts) { x0 = x[3 * p]; x1 = x[3 * p + 1]; x2 = x[3 * p + 2]; }
        }
    };

    // ---- prologue ----
    if (g0 < ngroups) {
        float x0, x1, x2;
        load_x(g0, x0, x1, x2);
        build_A(0, x0, x1, x2);
    }
    float xn0, xn1, xn2;
    load_x(g0 + gstep, xn0, xn1, xn2);
    bar_pair(barid);

    int buf = 0;
    for (int grp = g0; grp < ngroups; grp += gstep, buf ^= 1) {
        const int rowbase = grp << 5;

        float acc[2][4][4];
#pragma unroll
        for (int t = 0; t < 2; t++)
#pragma unroll
            for (int nt = 0; nt < 4; nt++)
#pragma unroll
                for (int c = 0; c < 4; c++) acc[t][nt][c] = 0.f;

        // ---- tile 0: ldsm, then fill latency with build_A(next) + prefetch ----
        {
            uint32_t ah[3][4];
            const uint32_t aBase = sbase + ((uint32_t)(buf * 4 + 2 * pr)) * AWARP + lmoff;
#pragma unroll
            for (int kt = 0; kt < 3; kt++)
                ldsm_x4(ah[kt], aBase + kt * 32);

            if (grp + gstep < ngroups)
                build_A(buf ^ 1, xn0, xn1, xn2);
            load_x(grp + 2 * gstep, xn0, xn1, xn2);

#pragma unroll
            for (int kt = 0; kt < 3; kt++)
#pragma unroll
                for (int nt = 0; nt < 4; nt++)
                    mma_f16(acc[0][nt], ah[kt], B[nt][kt]);
        }
        // ---- tile 1: ldsm, mma (short exposure; t0's MMA covers most of it) ----
        {
            uint32_t ah[3][4];
            const uint32_t aBase = sbase + ((uint32_t)(buf * 4 + 2 * pr + 1)) * AWARP + lmoff;
#pragma unroll
            for (int kt = 0; kt < 3; kt++)
                ldsm_x4(ah[kt], aBase + kt * 32);
#pragma unroll
            for (int kt = 0; kt < 3; kt++)
#pragma unroll
                for (int nt = 0; nt < 4; nt++)
                    mma_f16(acc[1][nt], ah[kt], B[nt][kt]);
        }

        // ---- epilogue: butterfly (xor 1) -> float4 -> STG.128 ----
        const bool ev = (tig & 1) == 0;
#pragma unroll
        for (int t = 0; t < 2; t++) {
            const int rowLo = rowbase + 16 * t + gid;
            const int rowHi = rowLo + 8;
#pragma unroll
            for (int ntp = 0; ntp < 2; ntp++) {
                const int ntA = 2 * ntp, ntB = ntA + 1;
                const int col = colbase +
                    (ev ? (16 * ntp + 2 * tig) : (16 * ntp + 8 + 2 * (tig - 1)));
#pragma unroll
                for (int hseg = 0; hseg < 2; hseg++) {
                    float m0 = acc[t][ntA][2 * hseg], m1 = acc[t][ntA][2 * hseg + 1];
                    float b0 = acc[t][ntB][2 * hseg], b1 = acc[t][ntB][2 * hseg + 1];
                    float s0 = ev ? b0 : m0;
                    float s1 = ev ? b1 : m1;
                    float r0 = __shfl_xor_sync(0xFFFFFFFFu, s0, 1);
                    float r1 = __shfl_xor_sync(0xFFFFFFFFu, s1, 1);
                    float4 v;
                    if (ev) v = make_float4(m0, m1, r0, r1);
                    else    v = make_float4(r0, r1, b0, b1);
                    const int row = hseg ? rowHi : rowLo;
                    if (row < npts)
                        *reinterpret_cast<float4*>(out + (size_t)row * COUT_ + col) = v;
                }
            }
        }

        bar_pair(barid);   // next group's A (both warps) complete
    }
}

extern "C" void kernel_launch(void* const* d_in, const int* in_sizes, int n_in,
                              void* d_out, int out_size)
{
    const float *x = nullptr, *kp = nullptr, *wt = nullptr, *sg = nullptr;
    int x_elems = 0;
    for (int i = 0; i < n_in; i++) {
        int s = in_sizes[i];
        if (s == 1)                    sg = (const float*)d_in[i];
        else if (s == JDIM)            kp = (const float*)d_in[i];
        else if (s == KP_ * 3 * COUT_) wt = (const float*)d_in[i];
        else { x = (const float*)d_in[i]; x_elems = s; }
    }
    const int npts    = x_elems / 3;
    const int ngroups = (npts + 31) >> 5;
    int grid = 148 * 5;
    int maxg = (ngroups + 1) / 2;
    if (grid > maxg) grid = maxg;

    kpconv_pipe2_kernel<<<grid, NTHR>>>(x, kp, wt, sg, (float*)d_out, npts);
}